// round 9
// baseline (speedup 1.0000x reference)
#include <cuda_runtime.h>
#include <cuda_bf16.h>
#include <mma.h>
#include <cstdint>
using namespace nvcuda;

constexpr int NTOK = 32768;
constexpr int HDIM = 1024;
constexpr int HR   = 512;
constexpr int CNUM = 4096;
constexpr int LD   = 40;        // bf16 elems per smem row: 32 data + 8 pad (80B, 16B-aligned)
constexpr int PL   = 128 * LD;  // elems per 128-row plane

__device__ float  g_h [(size_t)NTOK * HDIM];
__device__ float  g_z [(size_t)NTOK * HR];
__device__ float  g_h2[(size_t)NTOK * HDIM];
__device__ int    g_idx[NTOK];
__device__ float  g_cnorm[CNUM];
__device__ double g_part[NTOK];
// bf16 split planes [3][N][K], K contiguous
__device__ __nv_bfloat16 g_w1t[3ull * HDIM * HDIM];
__device__ __nv_bfloat16 g_w2t[3ull * HR   * HDIM];
__device__ __nv_bfloat16 g_cbs[3ull * CNUM * HR  ];
__device__ __nv_bfloat16 g_d1t[3ull * HDIM * HR  ];
__device__ __nv_bfloat16 g_d2t[3ull * HDIM * HDIM];

// ---------------- weight prep ----------------
__device__ __forceinline__ void split3(float f, uint16_t& h0, uint16_t& h1, uint16_t& h2) {
    h0 = __bfloat16_as_ushort(__float2bfloat16_rn(f));
    float r1 = f - __uint_as_float((uint32_t)h0 << 16);
    h1 = __bfloat16_as_ushort(__float2bfloat16_rn(r1));
    float r2 = r1 - __uint_as_float((uint32_t)h1 << 16);
    h2 = __bfloat16_as_ushort(__float2bfloat16_rn(r2));
}
// W[K,N] -> out[s][N][K]
__global__ void wsplit_t(const float* __restrict__ W, __nv_bfloat16* __restrict__ out,
                         int K, int N) {
    __shared__ float tile[32][33];
    int kb = blockIdx.y * 32, nb = blockIdx.x * 32;
    int tx = threadIdx.x, ty = threadIdx.y;
    for (int i = ty; i < 32; i += 8) tile[i][tx] = W[(size_t)(kb + i) * N + nb + tx];
    __syncthreads();
    size_t PS = (size_t)N * K;
    for (int i = ty; i < 32; i += 8) {
        uint16_t h0, h1, h2;
        split3(tile[tx][i], h0, h1, h2);
        size_t o = (size_t)(nb + i) * K + kb + tx;
        out[o] = __ushort_as_bfloat16(h0);
        out[PS + o] = __ushort_as_bfloat16(h1);
        out[2 * PS + o] = __ushort_as_bfloat16(h2);
    }
}
__global__ void csplit(const float* __restrict__ s, __nv_bfloat16* __restrict__ o, size_t n) {
    size_t i = (size_t)blockIdx.x * 256 + threadIdx.x;
    if (i < n) {
        uint16_t h0, h1, h2;
        split3(s[i], h0, h1, h2);
        o[i] = __ushort_as_bfloat16(h0);
        o[n + i] = __ushort_as_bfloat16(h1);
        o[2 * n + i] = __ushort_as_bfloat16(h2);
    }
}
__global__ void cnorm_kernel(const float* __restrict__ cb, float* __restrict__ cn) {
    int c = blockIdx.x;
    const float* row = cb + (size_t)c * HR;
    float s = 0.f;
    for (int k = threadIdx.x; k < HR; k += 128) { float v = row[k]; s += v * v; }
    __shared__ float sh[128];
    sh[threadIdx.x] = s; __syncthreads();
    for (int o = 64; o > 0; o >>= 1) {
        if (threadIdx.x < o) sh[threadIdx.x] += sh[threadIdx.x + o];
        __syncthreads();
    }
    if (threadIdx.x == 0) cn[c] = sh[0];
}

// ---------------- producers ----------------
// fp32 activations -> NS bf16 split planes (row-major [128][LD], 32 k-cols)
template <int NS>
__device__ __forceinline__ void prodA(const float* __restrict__ A, int row0, int K, int k0,
                                      __nv_bfloat16* dst, int tid) {
    const float* src = A + (size_t)row0 * K + k0;
    #pragma unroll
    for (int j = 0; j < 4; j++) {
        int g = tid + 256 * j;          // 128 rows x 8 float4
        int r = g >> 3, c = (g & 7) * 4;
        float4 v = *reinterpret_cast<const float4*>(src + (size_t)r * K + c);
        float cur[4] = {v.x, v.y, v.z, v.w};
        #pragma unroll
        for (int s = 0; s < NS; s++) {
            uint16_t h[4];
            #pragma unroll
            for (int e = 0; e < 4; e++) {
                h[e] = __bfloat16_as_ushort(__float2bfloat16_rn(cur[e]));
                cur[e] -= __uint_as_float((uint32_t)h[e] << 16);
            }
            uint2 w;
            w.x = (uint32_t)h[0] | ((uint32_t)h[1] << 16);
            w.y = (uint32_t)h[2] | ((uint32_t)h[3] << 16);
            *reinterpret_cast<uint2*>(dst + s * PL + r * LD + c) = w;
        }
    }
}
// bf16 B planes [N][K] -> smem [128][LD] (n rows, k cols)
template <int NS>
__device__ __forceinline__ void prodB(const __nv_bfloat16* __restrict__ Bp, size_t pstride,
                                      int n0, int K, int k0, __nv_bfloat16* dst, int tid) {
    #pragma unroll
    for (int s = 0; s < NS; s++) {
        const __nv_bfloat16* src = Bp + s * pstride + (size_t)n0 * K + k0;
        #pragma unroll
        for (int j = 0; j < 2; j++) {
            int g = tid + 256 * j;      // 128 n x 4 uint4
            int n = g >> 2, c = (g & 3) * 8;
            uint4 v = *reinterpret_cast<const uint4*>(src + (size_t)n * K + c);
            *reinterpret_cast<uint4*>(dst + s * PL + n * LD + c) = v;
        }
    }
}

// one 32-k compute step over all split terms; warp (wm 0..3, wn 0..1) owns 32x64
template <int NTERMS>
__device__ __forceinline__ void comp(const __nv_bfloat16* aB, const __nv_bfloat16* bB,
                                     int wm, int wn,
                                     wmma::fragment<wmma::accumulator,16,16,16,float> acc[2][4]) {
    const int ta[6] = {0, 0, 1, 1, 0, 2};
    const int tb[6] = {0, 1, 0, 1, 2, 0};
    #pragma unroll
    for (int term = 0; term < NTERMS; term++) {
        const __nv_bfloat16* pa = aB + ta[term] * PL;
        const __nv_bfloat16* pb = bB + tb[term] * PL;
        #pragma unroll
        for (int kk = 0; kk < 32; kk += 16) {
            wmma::fragment<wmma::matrix_a,16,16,16,__nv_bfloat16,wmma::row_major> fa[2];
            wmma::fragment<wmma::matrix_b,16,16,16,__nv_bfloat16,wmma::col_major> fb[4];
            #pragma unroll
            for (int i = 0; i < 2; i++)
                wmma::load_matrix_sync(fa[i], pa + (wm * 32 + i * 16) * LD + kk, LD);
            #pragma unroll
            for (int j = 0; j < 4; j++)
                wmma::load_matrix_sync(fb[j], pb + (wn * 64 + j * 16) * LD + kk, LD);
            #pragma unroll
            for (int i = 0; i < 2; i++)
                #pragma unroll
                for (int j = 0; j < 4; j++)
                    wmma::mma_sync(acc[i][j], fa[i], fb[j], acc[i][j]);
        }
    }
}

// ---------------- GEMM: C = act(A @ Bsplits + bias) ----------------
template <int NTERMS, bool RELU>
__global__ void __launch_bounds__(256)
gemm_wmma(const float* __restrict__ A, const __nv_bfloat16* __restrict__ Bs, size_t planeStride,
          const float* __restrict__ bias, float* __restrict__ C, int K, int Ntot) {
    constexpr int NS = (NTERMS == 6) ? 3 : 2;
    extern __shared__ __align__(16) char smem[];
    __nv_bfloat16* sp = reinterpret_cast<__nv_bfloat16*>(smem);
    const int tid = threadIdx.x, wid = tid >> 5;
    const int wm = wid >> 1, wn = wid & 1;
    const int row0 = blockIdx.y * 128, col0 = blockIdx.x * 128;

    wmma::fragment<wmma::accumulator,16,16,16,float> acc[2][4];
    #pragma unroll
    for (int i = 0; i < 2; i++)
        #pragma unroll
        for (int j = 0; j < 4; j++) wmma::fill_fragment(acc[i][j], 0.f);

    const int T = K / 32;
    prodA<NS>(A, row0, K, 0, sp, tid);
    prodB<NS>(Bs, planeStride, col0, K, 0, sp + NS * PL, tid);
    __syncthreads();
    for (int t = 0; t < T; t++) {
        int b = t & 1;
        __nv_bfloat16* cur = sp + b * 2 * NS * PL;
        __nv_bfloat16* nxt = sp + (b ^ 1) * 2 * NS * PL;
        if (t + 1 < T) {
            prodA<NS>(A, row0, K, (t + 1) * 32, nxt, tid);
            prodB<NS>(Bs, planeStride, col0, K, (t + 1) * 32, nxt + NS * PL, tid);
        }
        comp<NTERMS>(cur, cur + NS * PL, wm, wn, acc);
        __syncthreads();
    }

    // epilogue via smem (aliases pipeline buffers; all compute done)
    float* sC = reinterpret_cast<float*>(smem);
    #pragma unroll
    for (int i = 0; i < 2; i++)
        #pragma unroll
        for (int j = 0; j < 4; j++)
            wmma::store_matrix_sync(sC + (wm * 32 + i * 16) * 132 + (wn * 64 + j * 16),
                                    acc[i][j], 132, wmma::mem_row_major);
    __syncthreads();
    #pragma unroll
    for (int j2 = 0; j2 < 16; j2++) {
        int g = tid + 256 * j2;
        int row = g >> 5, c4 = (g & 31) * 4;
        float4 bv = *reinterpret_cast<const float4*>(&bias[col0 + c4]);
        float4 v;
        v.x = sC[row * 132 + c4 + 0] + bv.x;
        v.y = sC[row * 132 + c4 + 1] + bv.y;
        v.z = sC[row * 132 + c4 + 2] + bv.z;
        v.w = sC[row * 132 + c4 + 3] + bv.w;
        if (RELU) {
            v.x = fmaxf(v.x, 0.f); v.y = fmaxf(v.y, 0.f);
            v.z = fmaxf(v.z, 0.f); v.w = fmaxf(v.w, 0.f);
        }
        *reinterpret_cast<float4*>(&C[(size_t)(row0 + row) * Ntot + col0 + c4]) = v;
    }
}

// ---------------- distance + fused argmin ----------------
__device__ __forceinline__ unsigned int f32_orderable(float f) {
    unsigned int u = __float_as_uint(f);
    return (u & 0x80000000u) ? ~u : (u | 0x80000000u);
}
constexpr int D_PIPE = 4 * 3 * PL * 2;          // 122880 B pipeline
constexpr int D_SC   = D_PIPE;                  // float [128][132] = 67584 B
constexpr int D_CN   = D_SC + 128 * 132 * 4;    // 190464
constexpr int D_TOT  = D_CN + CNUM * 4;         // 206848

__global__ void __launch_bounds__(256)
dist_wmma(const float* __restrict__ Z, const __nv_bfloat16* __restrict__ CBs,
          const float* __restrict__ cn, int* __restrict__ out_idx) {
    constexpr int NS = 3;
    extern __shared__ __align__(16) char smem[];
    __nv_bfloat16* sp = reinterpret_cast<__nv_bfloat16*>(smem);
    float* sC  = reinterpret_cast<float*>(smem + D_SC);
    float* scn = reinterpret_cast<float*>(smem + D_CN);
    const int tid = threadIdx.x, wid = tid >> 5;
    const int wm = wid >> 1, wn = wid & 1;
    const int row0 = blockIdx.x * 128;

    for (int i = tid; i < CNUM; i += 256) scn[i] = cn[i];

    unsigned long long best = 0xFFFFFFFFFFFFFFFFull;
    const int T = HR / 32;     // 16 k-chunks per codeword block

    for (int c0 = 0; c0 < 32; c0++) {
        wmma::fragment<wmma::accumulator,16,16,16,float> acc[2][4];
        #pragma unroll
        for (int i = 0; i < 2; i++)
            #pragma unroll
            for (int j = 0; j < 4; j++) wmma::fill_fragment(acc[i][j], 0.f);

        __syncthreads();                       // scn ready (c0==0) / prev fold done
        prodA<NS>(Z, row0, HR, 0, sp, tid);
        prodB<NS>(CBs, (size_t)CNUM * HR, c0 * 128, HR, 0, sp + NS * PL, tid);
        __syncthreads();
        for (int t = 0; t < T; t++) {
            int b = t & 1;
            __nv_bfloat16* cur = sp + b * 2 * NS * PL;
            __nv_bfloat16* nxt = sp + (b ^ 1) * 2 * NS * PL;
            if (t + 1 < T) {
                prodA<NS>(Z, row0, HR, (t + 1) * 32, nxt, tid);
                prodB<NS>(CBs, (size_t)CNUM * HR, c0 * 128, HR, (t + 1) * 32, nxt + NS * PL, tid);
            }
            comp<6>(cur, cur + NS * PL, wm, wn, acc);
            __syncthreads();
        }
        #pragma unroll
        for (int i = 0; i < 2; i++)
            #pragma unroll
            for (int j = 0; j < 4; j++)
                wmma::store_matrix_sync(sC + (wm * 32 + i * 16) * 132 + (wn * 64 + j * 16),
                                        acc[i][j], 132, wmma::mem_row_major);
        __syncthreads();
        if (tid < 128) {
            for (int c = 0; c < 128; c++) {
                int cw = c0 * 128 + c;
                float d = scn[cw] - 2.0f * sC[tid * 132 + c];
                unsigned long long key =
                    ((unsigned long long)f32_orderable(d) << 32) | (unsigned)cw;
                if (key < best) best = key;
            }
        }
    }
    if (tid < 128) out_idx[row0 + tid] = (int)(best & 0xFFFFFFFFu);
}

// ---------------- gather + commit loss ----------------
__global__ void quant_commit(const float* __restrict__ Z, const float* __restrict__ CB,
                             const int* __restrict__ idx, float* __restrict__ out_q,
                             double* __restrict__ part) {
    int t = blockIdx.x;
    const float* cbrow = CB + (size_t)idx[t] * HR;
    const float* zrow  = Z + (size_t)t * HR;
    float* qrow        = out_q + (size_t)t * HR;
    double s = 0.0;
    for (int k = threadIdx.x; k < HR; k += 128) {
        float q = cbrow[k];
        float d = zrow[k] - q;
        qrow[k] = q;
        s += (double)d * (double)d;
    }
    __shared__ double sh[128];
    sh[threadIdx.x] = s; __syncthreads();
    for (int o = 64; o > 0; o >>= 1) {
        if (threadIdx.x < o) sh[threadIdx.x] += sh[threadIdx.x + o];
        __syncthreads();
    }
    if (threadIdx.x == 0) part[t] = sh[0];
}
__global__ void commit_reduce(const double* __restrict__ part, float* __restrict__ out) {
    __shared__ double sh[256];
    double s = 0.0;
    for (int i = threadIdx.x; i < NTOK; i += 256) s += part[i];
    sh[threadIdx.x] = s; __syncthreads();
    for (int o = 128; o > 0; o >>= 1) {
        if (threadIdx.x < o) sh[threadIdx.x] += sh[threadIdx.x + o];
        __syncthreads();
    }
    if (threadIdx.x == 0)
        out[0] = (float)(0.25 * sh[0] / ((double)NTOK * (double)HR));
}
__global__ void write_indices(const int* __restrict__ idx, float* __restrict__ out) {
    int i = blockIdx.x * blockDim.x + threadIdx.x;
    if (i < NTOK) out[i] = (float)idx[i];
}

// ---------------------------------------------------------------------------
extern "C" void kernel_launch(void* const* d_in, const int* in_sizes, int n_in,
                              void* d_out, int out_size) {
    const float* x      = (const float*)d_in[0];
    const float* enc_w1 = (const float*)d_in[1];
    const float* enc_b1 = (const float*)d_in[2];
    const float* enc_w2 = (const float*)d_in[3];
    const float* enc_b2 = (const float*)d_in[4];
    const float* cb     = (const float*)d_in[5];
    const float* dec_w1 = (const float*)d_in[6];
    const float* dec_b1 = (const float*)d_in[7];
    const float* dec_w2 = (const float*)d_in[8];
    const float* dec_b2 = (const float*)d_in[9];

    float* out   = (float*)d_out;
    float* recon = out;
    float* quant = out + (size_t)NTOK * HDIM;
    float* tokf  = quant + (size_t)NTOK * HR;
    float* lossf = tokf + NTOK;

    void* p;
    cudaGetSymbolAddress(&p, g_h);     float* h  = (float*)p;
    cudaGetSymbolAddress(&p, g_z);     float* z  = (float*)p;
    cudaGetSymbolAddress(&p, g_h2);    float* h2 = (float*)p;
    cudaGetSymbolAddress(&p, g_idx);   int*   idx = (int*)p;
    cudaGetSymbolAddress(&p, g_cnorm); float* cn  = (float*)p;
    cudaGetSymbolAddress(&p, g_part);  double* part = (double*)p;
    cudaGetSymbolAddress(&p, g_w1t); __nv_bfloat16* w1t = (__nv_bfloat16*)p;
    cudaGetSymbolAddress(&p, g_w2t); __nv_bfloat16* w2t = (__nv_bfloat16*)p;
    cudaGetSymbolAddress(&p, g_cbs); __nv_bfloat16* cbs = (__nv_bfloat16*)p;
    cudaGetSymbolAddress(&p, g_d1t); __nv_bfloat16* d1t = (__nv_bfloat16*)p;
    cudaGetSymbolAddress(&p, g_d2t); __nv_bfloat16* d2t = (__nv_bfloat16*)p;

    const int SMEM_G6 = 4 * 3 * PL * 2;   // 122880 B (NS=3 double-buffered A+B)
    const int SMEM_G3 = 4 * 2 * PL * 2;   // 81920 B  (NS=2)
    cudaFuncSetAttribute(gemm_wmma<6, true >, cudaFuncAttributeMaxDynamicSharedMemorySize, SMEM_G6);
    cudaFuncSetAttribute(gemm_wmma<6, false>, cudaFuncAttributeMaxDynamicSharedMemorySize, SMEM_G6);
    cudaFuncSetAttribute(gemm_wmma<3, true >, cudaFuncAttributeMaxDynamicSharedMemorySize, SMEM_G3);
    cudaFuncSetAttribute(gemm_wmma<3, false>, cudaFuncAttributeMaxDynamicSharedMemorySize, SMEM_G3);
    cudaFuncSetAttribute(dist_wmma, cudaFuncAttributeMaxDynamicSharedMemorySize, D_TOT);

    // prep: split/transpose weights + codebook, codebook norms
    wsplit_t<<<dim3(32, 32), dim3(32, 8)>>>(enc_w1, w1t, HDIM, HDIM);
    wsplit_t<<<dim3(16, 32), dim3(32, 8)>>>(enc_w2, w2t, HDIM, HR);
    wsplit_t<<<dim3(32, 16), dim3(32, 8)>>>(dec_w1, d1t, HR, HDIM);
    wsplit_t<<<dim3(32, 32), dim3(32, 8)>>>(dec_w2, d2t, HDIM, HDIM);
    csplit<<<(CNUM * HR + 255) / 256, 256>>>(cb, cbs, (size_t)CNUM * HR);
    cnorm_kernel<<<CNUM, 128>>>(cb, cn);

    // encoder (6-term split = fp32 accuracy)
    gemm_wmma<6, true ><<<dim3(HDIM / 128, NTOK / 128), 256, SMEM_G6>>>(
        x, w1t, (size_t)HDIM * HDIM, enc_b1, h, HDIM, HDIM);
    gemm_wmma<6, false><<<dim3(HR / 128, NTOK / 128), 256, SMEM_G6>>>(
        h, w2t, (size_t)HR * HDIM, enc_b2, z, HDIM, HR);

    // nearest codebook + gather + commit
    dist_wmma<<<NTOK / 128, 256, D_TOT>>>(z, cbs, cn, idx);
    quant_commit<<<NTOK, 128>>>(z, cb, idx, quant, part);
    write_indices<<<NTOK / 256, 256>>>(idx, tokf);
    commit_reduce<<<1, 256>>>(part, lossf);

    // decoder (3-term split, tolerance 1e-3)
    gemm_wmma<3, true ><<<dim3(HDIM / 128, NTOK / 128), 256, SMEM_G3>>>(
        quant, d1t, (size_t)HDIM * HR, dec_b1, h2, HR, HDIM);
    gemm_wmma<3, false><<<dim3(HDIM / 128, NTOK / 128), 256, SMEM_G3>>>(
        h2, d2t, (size_t)HDIM * HDIM, dec_b2, recon, HDIM, HDIM);
}